// round 1
// baseline (speedup 1.0000x reference)
#include <cuda_runtime.h>
#include <cuda_bf16.h>

// y = (x + 1) * 2/3 ; if y > 0 then y -= 5
// Pure HBM-streaming elementwise kernel: float4 vectorized, grid-stride.

__device__ __forceinline__ float f(float x) {
    const float c = 2.0f / 3.0f;
    float y = fmaf(x, c, c);        // (x+1)*2/3 == x*c + c
    return y > 0.0f ? y - 5.0f : y; // FADD + FSEL, branchless
}

__global__ void __launch_bounds__(256) ew_kernel(const float4* __restrict__ in,
                                                 float4* __restrict__ out,
                                                 int n4) {
    int i = blockIdx.x * blockDim.x + threadIdx.x;
    int stride = gridDim.x * blockDim.x;
    // unroll-by-2 grid-stride: two independent LDG.128 in flight per iter
    for (; i + stride < n4; i += 2 * stride) {
        float4 a = in[i];
        float4 b = in[i + stride];
        float4 ra = make_float4(f(a.x), f(a.y), f(a.z), f(a.w));
        float4 rb = make_float4(f(b.x), f(b.y), f(b.z), f(b.w));
        out[i] = ra;
        out[i + stride] = rb;
    }
    if (i < n4) {
        float4 a = in[i];
        out[i] = make_float4(f(a.x), f(a.y), f(a.z), f(a.w));
    }
}

extern "C" void kernel_launch(void* const* d_in, const int* in_sizes, int n_in,
                              void* d_out, int out_size) {
    const float* x = (const float*)d_in[0];
    float* y = (float*)d_out;
    int n = in_sizes[0];          // 67108864, divisible by 4
    int n4 = n >> 2;              // 16M float4s

    const int threads = 256;
    // ~8 CTAs per SM resident-equivalent work split; 148 SMs
    int blocks = 148 * 8 * 4;     // 4736 blocks -> each handles ~3.5K float4s
    ew_kernel<<<blocks, threads>>>((const float4*)x, (float4*)y, n4);
}